// round 1
// baseline (speedup 1.0000x reference)
#include <cuda_runtime.h>
#include <math.h>

#define NUM_PRIORS  3000
#define NUM_CLASSES 21
#define TOP_K       200
#define BATCH       256
#define TPB         256
#define KPT         12      // ceil(3000 / 256)
#define CONF_THRESH 0.01f
#define NMS_THRESH  0.45f

// -------------------------------------------------------------------------
// Zero the whole output tensor (background class rows + post-exhaustion rows
// stay zero; the NMS kernel overwrites only valid rows).
// -------------------------------------------------------------------------
__global__ void zero_out_kernel(float4* __restrict__ out, int n4)
{
    int i = blockIdx.x * blockDim.x + threadIdx.x;
    int stride = gridDim.x * blockDim.x;
    float4 z = make_float4(0.f, 0.f, 0.f, 0.f);
    for (; i < n4; i += stride) out[i] = z;
}

// -------------------------------------------------------------------------
// One CTA per (batch, foreground-class) pair. All 3000 (score, box, area)
// tuples live in registers, strided element e = k*256 + tid.
// Each of the <=200 greedy steps:
//   1. register-local argmax (strict >, keeps lowest k => lowest index)
//   2. warp shfl-xor reduce with lowest-global-index tie-break
//   3. cross-warp reduce of 8 partials (redundantly by every thread)
//   4. owner thread publishes winning box via shared, kills its score,
//      writes the output row
//   5. everyone suppresses its own registers by IoU > 0.45
// Early uniform exit when the max score is -inf (candidate set exhausted).
// -------------------------------------------------------------------------
__global__ __launch_bounds__(TPB, 2)
void nms_kernel(const float* __restrict__ loc_data,
                const float* __restrict__ conf_data,
                const float* __restrict__ priors,
                float* __restrict__ out)
{
    const int bc  = blockIdx.x;
    const int b   = bc / (NUM_CLASSES - 1);
    const int c   = bc % (NUM_CLASSES - 1) + 1;   // skip background class 0
    const int tid = threadIdx.x;
    const int warp = tid >> 5;
    const int lane = tid & 31;

    const float NEG = -INFINITY;

    float sc[KPT], bx1[KPT], by1[KPT], bx2[KPT], by2[KPT], ar[KPT];

    const float4* locb = (const float4*)loc_data + (size_t)b * NUM_PRIORS;
    const float4* pri  = (const float4*)priors;
    const float*  confb = conf_data + (size_t)b * NUM_PRIORS * NUM_CLASSES + c;

    // ---- decode + score gather -----------------------------------------
    #pragma unroll
    for (int k = 0; k < KPT; k++) {
        int e = k * TPB + tid;
        if (e < NUM_PRIORS) {
            float4 l = locb[e];
            float4 p = pri[e];
            float cx = p.x + l.x * 0.1f * p.z;
            float cy = p.y + l.y * 0.1f * p.w;
            float w  = p.z * expf(l.z * 0.2f);
            float h  = p.w * expf(l.w * 0.2f);
            bx1[k] = cx - w * 0.5f;
            by1[k] = cy - h * 0.5f;
            bx2[k] = cx + w * 0.5f;
            by2[k] = cy + h * 0.5f;
            // area from corner differences, exactly as the reference does
            ar[k]  = (bx2[k] - bx1[k]) * (by2[k] - by1[k]);
            float s = confb[(size_t)e * NUM_CLASSES];
            sc[k] = (s > CONF_THRESH) ? s : NEG;
        } else {
            sc[k] = NEG;
            bx1[k] = by1[k] = bx2[k] = by2[k] = 0.f;
            ar[k] = 0.f;
        }
    }

    __shared__ float  s_ps[TPB / 32];
    __shared__ int    s_pe[TPB / 32];
    __shared__ float4 s_box;

    float* orow = out + ((size_t)b * NUM_CLASSES + c) * TOP_K * 5;

    for (int it = 0; it < TOP_K; it++) {
        // 1. register-local argmax (strict >: first occurrence wins)
        float ls = sc[0];
        int   lk = 0;
        #pragma unroll
        for (int k = 1; k < KPT; k++)
            if (sc[k] > ls) { ls = sc[k]; lk = k; }
        int le = lk * TPB + tid;

        // 2. warp butterfly reduce, tie-break lowest global index
        #pragma unroll
        for (int off = 16; off; off >>= 1) {
            float os = __shfl_xor_sync(0xffffffffu, ls, off);
            int   oe = __shfl_xor_sync(0xffffffffu, le, off);
            if (os > ls || (os == ls && oe < le)) { ls = os; le = oe; }
        }
        if (lane == 0) { s_ps[warp] = ls; s_pe[warp] = le; }
        __syncthreads();

        // 3. cross-warp reduce (every thread, redundant => uniform result)
        float bs = s_ps[0];
        int   be = s_pe[0];
        #pragma unroll
        for (int w = 1; w < TPB / 32; w++) {
            float os = s_ps[w];
            int   oe = s_pe[w];
            if (os > bs || (os == bs && oe < be)) { bs = os; be = oe; }
        }

        // exhausted: all remaining scores are -inf -> rest of rows stay zero
        if (!(bs > CONF_THRESH)) break;

        // 4. owner publishes the winning box, kills it, writes output row
        if (tid == (be & (TPB - 1))) {
            int k = be >> 8;   // TPB == 256
            s_box = make_float4(bx1[k], by1[k], bx2[k], by2[k]);
            sc[k] = NEG;
            float* r = orow + it * 5;
            r[0] = bs;
            r[1] = bx1[k];
            r[2] = by1[k];
            r[3] = bx2[k];
            r[4] = by2[k];
        }
        __syncthreads();

        // 5. IoU suppression against own registers
        float4 B  = s_box;
        float  A1 = (B.z - B.x) * (B.w - B.y);
        #pragma unroll
        for (int k = 0; k < KPT; k++) {
            float ltx = fmaxf(B.x, bx1[k]);
            float lty = fmaxf(B.y, by1[k]);
            float rbx = fminf(B.z, bx2[k]);
            float rby = fminf(B.w, by2[k]);
            float iw  = fmaxf(rbx - ltx, 0.f);
            float ih  = fmaxf(rby - lty, 0.f);
            float inter = iw * ih;
            float uni   = A1 + ar[k] - inter;
            if (inter > NMS_THRESH * uni) sc[k] = NEG;
        }
        // no sync needed here: next iteration's first shared write happens
        // after this loop, and every read of s_ps/s_box from this iteration
        // is separated from the next write by the syncs above.
    }
}

extern "C" void kernel_launch(void* const* d_in, const int* in_sizes, int n_in,
                              void* d_out, int out_size)
{
    const float* loc_data  = (const float*)d_in[0];
    const float* conf_data = (const float*)d_in[1];
    const float* priors    = (const float*)d_in[2];
    float* out = (float*)d_out;

    int n4 = out_size / 4;   // 5,376,000 floats -> 1,344,000 float4
    zero_out_kernel<<<1024, 256>>>((float4*)out, n4);

    int nblocks = BATCH * (NUM_CLASSES - 1);   // 5120
    nms_kernel<<<nblocks, TPB>>>(loc_data, conf_data, priors, out);
}

// round 2
// speedup vs baseline: 1.0002x; 1.0002x over previous
#include <cuda_runtime.h>
#include <math.h>

#define NUM_PRIORS  3000
#define NUM_CLASSES 21
#define TOP_K       200
#define BATCH       256
#define TPB         256
#define KPT         12      // ceil(3000 / 256)
#define CONF_THRESH 0.01f
#define NMS_THRESH  0.45f

// -------------------------------------------------------------------------
// Zero the whole output tensor (background class rows + post-exhaustion rows
// stay zero; the NMS kernel overwrites only valid rows).
// -------------------------------------------------------------------------
__global__ void zero_out_kernel(float4* __restrict__ out, int n4)
{
    int i = blockIdx.x * blockDim.x + threadIdx.x;
    int stride = gridDim.x * blockDim.x;
    float4 z = make_float4(0.f, 0.f, 0.f, 0.f);
    for (; i < n4; i += stride) out[i] = z;
}

// -------------------------------------------------------------------------
// One CTA per (batch, foreground-class) pair. All 3000 (score, box, area)
// tuples live in registers, strided element e = k*256 + tid.
// Each of the <=200 greedy steps:
//   1. register-local argmax (strict >, keeps lowest k => lowest index)
//   2. warp shfl-xor reduce with lowest-global-index tie-break
//   3. cross-warp reduce of 8 partials (redundantly by every thread)
//   4. owner thread publishes winning box via shared, kills its score,
//      writes the output row
//   5. everyone suppresses its own registers by IoU > 0.45
// Early uniform exit when the max score is -inf (candidate set exhausted).
// -------------------------------------------------------------------------
__global__ __launch_bounds__(TPB, 2)
void nms_kernel(const float* __restrict__ loc_data,
                const float* __restrict__ conf_data,
                const float* __restrict__ priors,
                float* __restrict__ out)
{
    const int bc  = blockIdx.x;
    const int b   = bc / (NUM_CLASSES - 1);
    const int c   = bc % (NUM_CLASSES - 1) + 1;   // skip background class 0
    const int tid = threadIdx.x;
    const int warp = tid >> 5;
    const int lane = tid & 31;

    const float NEG = -INFINITY;

    float sc[KPT], bx1[KPT], by1[KPT], bx2[KPT], by2[KPT], ar[KPT];

    const float4* locb = (const float4*)loc_data + (size_t)b * NUM_PRIORS;
    const float4* pri  = (const float4*)priors;
    const float*  confb = conf_data + (size_t)b * NUM_PRIORS * NUM_CLASSES + c;

    // ---- decode + score gather -----------------------------------------
    #pragma unroll
    for (int k = 0; k < KPT; k++) {
        int e = k * TPB + tid;
        if (e < NUM_PRIORS) {
            float4 l = locb[e];
            float4 p = pri[e];
            float cx = p.x + l.x * 0.1f * p.z;
            float cy = p.y + l.y * 0.1f * p.w;
            float w  = p.z * expf(l.z * 0.2f);
            float h  = p.w * expf(l.w * 0.2f);
            bx1[k] = cx - w * 0.5f;
            by1[k] = cy - h * 0.5f;
            bx2[k] = cx + w * 0.5f;
            by2[k] = cy + h * 0.5f;
            // area from corner differences, exactly as the reference does
            ar[k]  = (bx2[k] - bx1[k]) * (by2[k] - by1[k]);
            float s = confb[(size_t)e * NUM_CLASSES];
            sc[k] = (s > CONF_THRESH) ? s : NEG;
        } else {
            sc[k] = NEG;
            bx1[k] = by1[k] = bx2[k] = by2[k] = 0.f;
            ar[k] = 0.f;
        }
    }

    __shared__ float  s_ps[TPB / 32];
    __shared__ int    s_pe[TPB / 32];
    __shared__ float4 s_box;

    float* orow = out + ((size_t)b * NUM_CLASSES + c) * TOP_K * 5;

    for (int it = 0; it < TOP_K; it++) {
        // 1. register-local argmax (strict >: first occurrence wins)
        float ls = sc[0];
        int   lk = 0;
        #pragma unroll
        for (int k = 1; k < KPT; k++)
            if (sc[k] > ls) { ls = sc[k]; lk = k; }
        int le = lk * TPB + tid;

        // 2. warp butterfly reduce, tie-break lowest global index
        #pragma unroll
        for (int off = 16; off; off >>= 1) {
            float os = __shfl_xor_sync(0xffffffffu, ls, off);
            int   oe = __shfl_xor_sync(0xffffffffu, le, off);
            if (os > ls || (os == ls && oe < le)) { ls = os; le = oe; }
        }
        if (lane == 0) { s_ps[warp] = ls; s_pe[warp] = le; }
        __syncthreads();

        // 3. cross-warp reduce (every thread, redundant => uniform result)
        float bs = s_ps[0];
        int   be = s_pe[0];
        #pragma unroll
        for (int w = 1; w < TPB / 32; w++) {
            float os = s_ps[w];
            int   oe = s_pe[w];
            if (os > bs || (os == bs && oe < be)) { bs = os; be = oe; }
        }

        // exhausted: all remaining scores are -inf -> rest of rows stay zero
        if (!(bs > CONF_THRESH)) break;

        // 4. owner publishes the winning box, kills it, writes output row
        if (tid == (be & (TPB - 1))) {
            int k = be >> 8;   // TPB == 256
            s_box = make_float4(bx1[k], by1[k], bx2[k], by2[k]);
            sc[k] = NEG;
            float* r = orow + it * 5;
            r[0] = bs;
            r[1] = bx1[k];
            r[2] = by1[k];
            r[3] = bx2[k];
            r[4] = by2[k];
        }
        __syncthreads();

        // 5. IoU suppression against own registers
        float4 B  = s_box;
        float  A1 = (B.z - B.x) * (B.w - B.y);
        #pragma unroll
        for (int k = 0; k < KPT; k++) {
            float ltx = fmaxf(B.x, bx1[k]);
            float lty = fmaxf(B.y, by1[k]);
            float rbx = fminf(B.z, bx2[k]);
            float rby = fminf(B.w, by2[k]);
            float iw  = fmaxf(rbx - ltx, 0.f);
            float ih  = fmaxf(rby - lty, 0.f);
            float inter = iw * ih;
            float uni   = A1 + ar[k] - inter;
            if (inter > NMS_THRESH * uni) sc[k] = NEG;
        }
        // no sync needed here: next iteration's first shared write happens
        // after this loop, and every read of s_ps/s_box from this iteration
        // is separated from the next write by the syncs above.
    }
}

extern "C" void kernel_launch(void* const* d_in, const int* in_sizes, int n_in,
                              void* d_out, int out_size)
{
    const float* loc_data  = (const float*)d_in[0];
    const float* conf_data = (const float*)d_in[1];
    const float* priors    = (const float*)d_in[2];
    float* out = (float*)d_out;

    int n4 = out_size / 4;   // 5,376,000 floats -> 1,344,000 float4
    zero_out_kernel<<<1024, 256>>>((float4*)out, n4);

    int nblocks = BATCH * (NUM_CLASSES - 1);   // 5120
    nms_kernel<<<nblocks, TPB>>>(loc_data, conf_data, priors, out);
}

// round 5
// speedup vs baseline: 1.5449x; 1.5445x over previous
#include <cuda_runtime.h>
#include <math.h>
#include <stdint.h>

#define NUM_PRIORS  3000
#define NUM_CLASSES 21
#define TOP_K       200
#define BATCH       256
#define TPB         256
#define SORT_N      4096
#define CONF_THRESH 0.01f
#define NMS_THRESH  0.45f

// ---- dynamic shared memory layout (bytes) ----
#define OFF_BOX    0          // float4[3000]           48000
#define OFF_KEYS   48000      // uint64[4096]           32768
#define OFF_ACCB   80768      // float4[200]             3200
#define OFF_ACCA   83968      // float[200]               800
#define OFF_WBOX   84768      // float4[32]               512
#define OFF_WAR    85280      // float[32]                128
#define OFF_WSC    85408      // float[32]                128
#define OFF_WBAD   85536      // int[32]                  128
#define OFF_WOVR   85664      // unsigned[32]             128
#define OFF_MISC   85792      // unsigned[8]               32
#define SMEM_BYTES 85824

__global__ void zero_out_kernel(float4* __restrict__ out, int n4)
{
    int i = blockIdx.x * blockDim.x + threadIdx.x;
    int stride = gridDim.x * blockDim.x;
    float4 z = make_float4(0.f, 0.f, 0.f, 0.f);
    for (; i < n4; i += stride) out[i] = z;
}

// identical arithmetic to the previously passing kernel's IoU test
__device__ __forceinline__ bool overlaps(float4 A, float aA, float4 B, float aB)
{
    float ltx = fmaxf(A.x, B.x);
    float lty = fmaxf(A.y, B.y);
    float rbx = fminf(A.z, B.z);
    float rby = fminf(A.w, B.w);
    float iw  = fmaxf(rbx - ltx, 0.f);
    float ih  = fmaxf(rby - lty, 0.f);
    float inter = iw * ih;
    float uni   = aA + aB - inter;
    return inter > NMS_THRESH * uni;
}

// Greedy NMS == scan candidates in (score desc, index asc) order, accept iff
// no IoU>thresh overlap with any already-accepted box, stop at TOP_K accepted.
// One CTA per (batch, foreground class). Boxes + sort keys live in shared.
__global__ void __launch_bounds__(TPB, 2)
nms_kernel(const float* __restrict__ loc_data,
           const float* __restrict__ conf_data,
           const float* __restrict__ priors,
           float* __restrict__ out)
{
    extern __shared__ char sm[];
    float4*             box  = (float4*)(sm + OFF_BOX);
    unsigned long long* keys = (unsigned long long*)(sm + OFF_KEYS);
    float4*             accb = (float4*)(sm + OFF_ACCB);
    float*              acca = (float*)(sm + OFF_ACCA);
    float4*             wbox = (float4*)(sm + OFF_WBOX);
    float*              war  = (float*)(sm + OFF_WAR);
    float*              wsc  = (float*)(sm + OFF_WSC);
    int*                wbad = (int*)(sm + OFF_WBAD);
    unsigned*           wovr = (unsigned*)(sm + OFF_WOVR);
    unsigned*           misc = (unsigned*)(sm + OFF_MISC);

    const int bc  = blockIdx.x;
    const int b   = bc / (NUM_CLASSES - 1);
    const int cls = bc % (NUM_CLASSES - 1) + 1;     // skip background class 0
    const int tid = threadIdx.x;

    const float4* locb  = (const float4*)loc_data + (size_t)b * NUM_PRIORS;
    const float4* pri   = (const float4*)priors;
    const float*  confb = conf_data + ((size_t)b * NUM_PRIORS) * NUM_CLASSES + cls;

    // ---- decode boxes + build sort keys --------------------------------
    for (int e = tid; e < NUM_PRIORS; e += TPB) {
        float4 l = locb[e];
        float4 p = pri[e];
        float cx = p.x + l.x * 0.1f * p.z;
        float cy = p.y + l.y * 0.1f * p.w;
        float w  = p.z * expf(l.z * 0.2f);
        float h  = p.w * expf(l.w * 0.2f);
        box[e] = make_float4(cx - w * 0.5f, cy - h * 0.5f,
                             cx + w * 0.5f, cy + h * 0.5f);
        float s = confb[(size_t)e * NUM_CLASSES];
        // valid scores are positive floats -> bit pattern is order-monotonic.
        // low word ~e: equal scores sort by ascending original index (desc key).
        unsigned sb = (s > CONF_THRESH) ? __float_as_uint(s) : 0u;
        keys[e] = ((unsigned long long)sb << 32) | (unsigned)(~e);
    }
    for (int e = NUM_PRIORS + tid; e < SORT_N; e += TPB) keys[e] = 0ull;

    // ---- bitonic sort, descending --------------------------------------
    for (unsigned k = 2; k <= SORT_N; k <<= 1) {
        for (unsigned j = k >> 1; j > 0; j >>= 1) {
            __syncthreads();
            for (unsigned i = tid; i < SORT_N; i += TPB) {
                unsigned ixj = i ^ j;
                if (ixj > i) {
                    unsigned long long a = keys[i];
                    unsigned long long bk = keys[ixj];
                    bool desc = (i & k) == 0;
                    if (desc ? (a < bk) : (a > bk)) {
                        keys[i] = bk;
                        keys[ixj] = a;
                    }
                }
            }
        }
    }

    // ---- windowed sequential-acceptance scan ---------------------------
    float* orow = out + ((size_t)b * NUM_CLASSES + cls) * TOP_K * 5;
    int nacc = 0, cursor = 0;
    const int c = tid & 31;      // this thread's window candidate
    const int g = tid >> 5;      // group 0..7

    while (true) {
        __syncthreads();   // B1: prev iteration's accept-writes complete
        if (tid < 32) {
            unsigned long long kk = keys[cursor + tid];
            unsigned sb = (unsigned)(kk >> 32);
            if (sb) {
                int idx = (int)(~(unsigned)kk);
                float4 bb = box[idx];
                wbox[tid] = bb;
                war[tid]  = (bb.z - bb.x) * (bb.w - bb.y);
                wsc[tid]  = __uint_as_float(sb);
            } else {
                wbox[tid] = make_float4(0.f, 0.f, 0.f, 0.f);
                war[tid]  = 0.f;
                wsc[tid]  = -1.0f;          // invalid marker
            }
            wbad[tid] = 0;
            wovr[tid] = 0u;
        }
        __syncthreads();   // B2: window staged

        float csc  = wsc[c];
        float4 cb  = wbox[c];
        float  car = war[c];

        // candidate c vs accepted set (a strided over 8 thread-groups)
        if (csc >= 0.f && nacc > 0) {
            bool bad = false;
            for (int a = g; a < nacc; a += 8) {
                if (overlaps(accb[a], acca[a], cb, car)) { bad = true; break; }
            }
            if (bad) atomicOr(&wbad[c], 1);
        }
        // intra-window overlap mask: bits c1 < c that overlap c
        if (csc >= 0.f) {
            unsigned m = 0;
            #pragma unroll
            for (int c1 = g; c1 < 32; c1 += 8) {
                if (c1 < c && wsc[c1] >= 0.f &&
                    overlaps(wbox[c1], war[c1], cb, car))
                    m |= 1u << c1;
            }
            if (m) atomicOr(&wovr[c], m);
        }
        __syncthreads();   // B3: masks complete

        // serial resolution (exact sequential acceptance semantics)
        if (tid == 0) {
            unsigned m = 0;
            int cnt = 0, lim = TOP_K - nacc, dn = 0;
            #pragma unroll 1
            for (int i = 0; i < 32; i++) {
                if (wsc[i] < 0.f) { dn = 1; break; }   // sorted: rest invalid
                if (cnt >= lim) break;
                if (!wbad[i] && ((wovr[i] & m) == 0u)) { m |= 1u << i; cnt++; }
            }
            misc[0] = m;
            misc[1] = (unsigned)dn;
        }
        __syncthreads();   // B4: accmask visible

        unsigned m = misc[0];
        int dn = (int)misc[1];
        if (tid < 32 && ((m >> tid) & 1u)) {
            int slot = nacc + __popc(m & ((1u << tid) - 1u));
            float4 bb = wbox[tid];
            accb[slot] = bb;
            acca[slot] = war[tid];
            float* r = orow + slot * 5;
            r[0] = wsc[tid];
            r[1] = bb.x; r[2] = bb.y; r[3] = bb.z; r[4] = bb.w;
        }
        nacc   += __popc(m);
        cursor += 32;
        if (dn || nacc >= TOP_K || cursor >= SORT_N) break;
    }
}

extern "C" void kernel_launch(void* const* d_in, const int* in_sizes, int n_in,
                              void* d_out, int out_size)
{
    const float* loc_data  = (const float*)d_in[0];
    const float* conf_data = (const float*)d_in[1];
    const float* priors    = (const float*)d_in[2];
    float* out = (float*)d_out;

    zero_out_kernel<<<1024, 256>>>((float4*)out, out_size / 4);

    cudaFuncSetAttribute((const void*)nms_kernel,
                         cudaFuncAttributeMaxDynamicSharedMemorySize, SMEM_BYTES);
    int nblocks = BATCH * (NUM_CLASSES - 1);   // 5120
    nms_kernel<<<nblocks, TPB, SMEM_BYTES>>>(loc_data, conf_data, priors, out);
}

// round 6
// speedup vs baseline: 2.4136x; 1.5623x over previous
#include <cuda_runtime.h>
#include <math.h>

typedef unsigned long long ull;

#define NUM_PRIORS  3000
#define NUM_CLASSES 21
#define TOP_K       200
#define BATCH       256
#define TPB         512
#define SLOTS       8           // SORT_N / TPB
#define SORT_N      4096
#define CONF_THRESH 0.01f
#define NMS_THRESH  0.45f
#define FULLM       0xffffffffu

__global__ void zero_out_kernel(float4* __restrict__ out, int n4)
{
    int i = blockIdx.x * blockDim.x + threadIdx.x;
    int stride = gridDim.x * blockDim.x;
    float4 z = make_float4(0.f, 0.f, 0.f, 0.f);
    for (; i < n4; i += stride) out[i] = z;
}

// identical arithmetic to the passing kernels' IoU test
__device__ __forceinline__ bool overlaps(float4 A, float aA, float4 B, float aB)
{
    float ltx = fmaxf(A.x, B.x);
    float lty = fmaxf(A.y, B.y);
    float rbx = fminf(A.z, B.z);
    float rby = fminf(A.w, B.w);
    float iw  = fmaxf(rbx - ltx, 0.f);
    float ih  = fmaxf(rby - lty, 0.f);
    float inter = iw * ih;
    float uni   = aA + aB - inter;
    return inter > NMS_THRESH * uni;
}

// Greedy NMS == scan candidates in (score desc, index asc) order, accept iff
// no IoU>thresh overlap with an already-accepted box, stop at TOP_K.
// Sort: register-resident bitonic (shfl for j<=16, registers for j>=512,
// shared only for j in [32,256]). Boxes decoded lazily at window staging.
__global__ void __launch_bounds__(TPB, 2)
nms_kernel(const float* __restrict__ loc_data,
           const float* __restrict__ conf_data,
           const float* __restrict__ priors,
           float* __restrict__ out)
{
    __shared__ ull    keys[SORT_N];     // 32768 B
    __shared__ float4 accb[TOP_K];      //  3200 B
    __shared__ float  acca[TOP_K];      //   800 B
    __shared__ float4 wbox[32];
    __shared__ float  war[32];
    __shared__ float  wsc[32];
    __shared__ int    wbad[32];
    __shared__ unsigned wovr[32];
    __shared__ unsigned misc[2];

    const int bc  = blockIdx.x;
    const int b   = bc / (NUM_CLASSES - 1);
    const int cls = bc % (NUM_CLASSES - 1) + 1;   // skip background class 0
    const int t   = threadIdx.x;

    const float* confb = conf_data + ((size_t)b * NUM_PRIORS) * NUM_CLASSES + cls;

    // ---- build 64-bit sort keys in registers ---------------------------
    // hi = score bits (positive float -> order-monotonic; 0 if below thresh)
    // lo = ~idx (equal scores sort by ascending original index)
    ull K[SLOTS];
    #pragma unroll
    for (int s = 0; s < SLOTS; s++) {
        int e = s * TPB + t;
        unsigned sb = 0u;
        if (e < NUM_PRIORS) {
            float sc = confb[(size_t)e * NUM_CLASSES];
            if (sc > CONF_THRESH) sb = __float_as_uint(sc);
        }
        K[s] = ((ull)sb << 32) | (unsigned)(~e);
    }

    // ---- bitonic sort (descending), element e = s*TPB + t --------------
    for (unsigned k = 2; k <= SORT_N; k <<= 1) {
        bool descS[SLOTS];
        #pragma unroll
        for (int s = 0; s < SLOTS; s++)
            descS[s] = ((((unsigned)(s * TPB + t)) & k) == 0u);

        // register phases: stride j >= TPB (slot-stride inside the thread)
        for (unsigned j = k >> 1; j >= TPB; j >>= 1) {
            unsigned ds = j / TPB;
            #pragma unroll
            for (int s = 0; s < SLOTS; s++) {
                if (!(s & ds)) {
                    int p = s | (int)ds;
                    ull a = K[s], bb = K[p];
                    bool agtb = a > bb;
                    ull mx = agtb ? a : bb;
                    ull mn = agtb ? bb : a;
                    K[s] = descS[s] ? mx : mn;
                    K[p] = descS[s] ? mn : mx;
                }
            }
        }

        // shared phases: 32 <= j <= 256 (cross-warp thread strides)
        if (k > 32u) {
            #pragma unroll
            for (int s = 0; s < SLOTS; s++) keys[s * TPB + t] = K[s];
            __syncthreads();
            unsigned jstart = (k >> 1 < 256u) ? (k >> 1) : 256u;
            for (unsigned j = jstart; j >= 32u; j >>= 1) {
                #pragma unroll
                for (int s = 0; s < SLOTS; s++) {
                    unsigned i = (unsigned)(s * TPB + t);
                    unsigned ixj = i ^ j;
                    if (ixj > i) {
                        ull a = keys[i];
                        ull bb = keys[ixj];
                        bool desc = ((i & k) == 0u);
                        if (desc ? (a < bb) : (a > bb)) {
                            keys[i] = bb;
                            keys[ixj] = a;
                        }
                    }
                }
                __syncthreads();
            }
            #pragma unroll
            for (int s = 0; s < SLOTS; s++) K[s] = keys[s * TPB + t];
        }

        // shfl phases: j <= 16 (lane strides, no smem, no barrier)
        {
            unsigned jtop = (k >> 1 < 16u) ? (k >> 1) : 16u;
            for (unsigned j = jtop; j >= 1u; j >>= 1) {
                bool lower = ((t & (int)j) == 0);
                #pragma unroll
                for (int s = 0; s < SLOTS; s++) {
                    ull mine = K[s];
                    ull oth  = __shfl_xor_sync(FULLM, mine, j);
                    bool keepmax = (lower == descS[s]);
                    bool mgto = mine > oth;
                    K[s] = keepmax ? (mgto ? mine : oth) : (mgto ? oth : mine);
                }
            }
        }
    }
    // final dump of sorted keys for the scan
    #pragma unroll
    for (int s = 0; s < SLOTS; s++) keys[s * TPB + t] = K[s];

    // ---- windowed sequential-acceptance scan ---------------------------
    float* orow = out + ((size_t)b * NUM_CLASSES + cls) * TOP_K * 5;
    const float4* locb = (const float4*)loc_data + (size_t)b * NUM_PRIORS;
    const float4* pri  = (const float4*)priors;

    int nacc = 0, cursor = 0;
    const int c = t & 31;     // this thread's window candidate
    const int g = t >> 5;     // group 0..15 (== warp id)

    while (true) {
        __syncthreads();   // B1: prior reads done / sort dump visible
        if (t < 32) {
            ull kk = keys[cursor + t];
            unsigned sb = (unsigned)(kk >> 32);
            if (sb) {
                int idx = (int)~(unsigned)kk;
                float4 l = locb[idx];
                float4 p = pri[idx];
                float cx = p.x + l.x * 0.1f * p.z;
                float cy = p.y + l.y * 0.1f * p.w;
                float w  = p.z * expf(l.z * 0.2f);
                float h  = p.w * expf(l.w * 0.2f);
                float4 bb = make_float4(cx - w * 0.5f, cy - h * 0.5f,
                                        cx + w * 0.5f, cy + h * 0.5f);
                wbox[t] = bb;
                war[t]  = (bb.z - bb.x) * (bb.w - bb.y);
                wsc[t]  = __uint_as_float(sb);
            } else {
                wbox[t] = make_float4(0.f, 0.f, 0.f, 0.f);
                war[t]  = 0.f;
                wsc[t]  = -1.0f;          // invalid marker
            }
            wbad[t] = 0;
            wovr[t] = 0u;
        }
        __syncthreads();   // B2: window staged

        float csc = wsc[c];
        if (csc >= 0.f) {
            float4 cb  = wbox[c];
            float  car = war[c];
            // candidate c vs accepted set, strided over 16 warps
            bool bad = false;
            for (int a = g; a < nacc; a += 16)
                if (overlaps(accb[a], acca[a], cb, car)) { bad = true; break; }
            if (bad) atomicOr(&wbad[c], 1);
            // intra-window: bits c1 < c that overlap c
            unsigned m = 0;
            #pragma unroll
            for (int c1 = g; c1 < 32; c1 += 16) {
                if (c1 < c && wsc[c1] >= 0.f &&
                    overlaps(wbox[c1], war[c1], cb, car))
                    m |= 1u << c1;
            }
            if (m) atomicOr(&wovr[c], m);
        }
        __syncthreads();   // B3: masks complete

        // warp-0 register resolution (exact sequential acceptance)
        if (t < 32) {
            unsigned my_ovr  = wovr[t];
            bool my_bad      = (wbad[t] != 0);
            bool my_valid    = (wsc[t] >= 0.f);
            unsigned badmask = __ballot_sync(FULLM, my_bad);
            unsigned valmask = __ballot_sync(FULLM, my_valid);
            unsigned m = 0;
            int cnt = 0, dn = 0, lim = TOP_K - nacc;
            for (int i = 0; i < 32; i++) {
                unsigned ov = __shfl_sync(FULLM, my_ovr, i);  // uniform exec
                if (!((valmask >> i) & 1u)) { dn = 1; break; } // sorted: rest invalid
                if (cnt >= lim) break;
                if (!((badmask >> i) & 1u) && !(ov & m)) { m |= 1u << i; cnt++; }
            }
            if (t == 0) { misc[0] = m; misc[1] = (unsigned)dn; }
        }
        __syncthreads();   // B4: accept mask visible

        unsigned m = misc[0];
        int dn = (int)misc[1];
        if (t < 32 && ((m >> t) & 1u)) {
            int slot = nacc + __popc(m & ((1u << t) - 1u));
            float4 bb = wbox[t];
            accb[slot] = bb;
            acca[slot] = war[t];
            float* r = orow + slot * 5;
            r[0] = wsc[t];
            r[1] = bb.x; r[2] = bb.y; r[3] = bb.z; r[4] = bb.w;
        }
        nacc   += __popc(m);
        cursor += 32;
        if (dn || nacc >= TOP_K || cursor >= SORT_N) break;
    }
}

extern "C" void kernel_launch(void* const* d_in, const int* in_sizes, int n_in,
                              void* d_out, int out_size)
{
    const float* loc_data  = (const float*)d_in[0];
    const float* conf_data = (const float*)d_in[1];
    const float* priors    = (const float*)d_in[2];
    float* out = (float*)d_out;

    zero_out_kernel<<<1024, 256>>>((float4*)out, out_size / 4);

    int nblocks = BATCH * (NUM_CLASSES - 1);   // 5120
    nms_kernel<<<nblocks, TPB>>>(loc_data, conf_data, priors, out);
}

// round 7
// speedup vs baseline: 2.4356x; 1.0091x over previous
#include <cuda_runtime.h>
#include <math.h>

typedef unsigned long long ull;

#define NUM_PRIORS  3000
#define NUM_CLASSES 21
#define TOP_K       200
#define BATCH       256
#define TPB         512
#define SLOTS       8           // SORT_N / TPB
#define SORT_N      4096
#define DEC_N       2048        // decoded-box ring size (power of 2)
#define CONF_THRESH 0.01f
#define NMS_THRESH  0.45f
#define FULLM       0xffffffffu

// ---- dynamic shared memory layout (bytes) ----
#define OFF_SBOX 0          // float4[2048]   32768
#define OFF_ACCB 32768      // float4[200]     3200
#define OFF_KEYS 35968      // ull[4096]      32768
#define OFF_ACCA 68736      // float[200]       800
#define OFF_OVRT 69536      // unsigned[32]     128
#define OFF_BADP 69664      // unsigned[16]      64
#define OFF_MISC 69728      // unsigned[2]        8
#define SMEM_BYTES 69760

__global__ void zero_out_kernel(float4* __restrict__ out, int n4)
{
    int i = blockIdx.x * blockDim.x + threadIdx.x;
    int stride = gridDim.x * blockDim.x;
    float4 z = make_float4(0.f, 0.f, 0.f, 0.f);
    for (; i < n4; i += stride) out[i] = z;
}

// identical arithmetic to the passing kernels' IoU test
__device__ __forceinline__ bool overlaps(float4 A, float aA, float4 B, float aB)
{
    float ltx = fmaxf(A.x, B.x);
    float lty = fmaxf(A.y, B.y);
    float rbx = fminf(A.z, B.z);
    float rby = fminf(A.w, B.w);
    float iw  = fmaxf(rbx - ltx, 0.f);
    float ih  = fmaxf(rby - lty, 0.f);
    float inter = iw * ih;
    float uni   = aA + aB - inter;
    return inter > NMS_THRESH * uni;
}

__global__ void __launch_bounds__(TPB, 2)
nms_kernel(const float* __restrict__ loc_data,
           const float* __restrict__ conf_data,
           const float* __restrict__ priors,
           float* __restrict__ out)
{
    extern __shared__ char sm[];
    float4*   sbox = (float4*)(sm + OFF_SBOX);
    float4*   accb = (float4*)(sm + OFF_ACCB);
    ull*      keys = (ull*)(sm + OFF_KEYS);
    float*    acca = (float*)(sm + OFF_ACCA);
    unsigned* ovrT = (unsigned*)(sm + OFF_OVRT);
    unsigned* badp = (unsigned*)(sm + OFF_BADP);
    unsigned* misc = (unsigned*)(sm + OFF_MISC);

    const int bc  = blockIdx.x;
    const int b   = bc / (NUM_CLASSES - 1);
    const int cls = bc % (NUM_CLASSES - 1) + 1;   // skip background class 0
    const int t   = threadIdx.x;

    const float* confb = conf_data + ((size_t)b * NUM_PRIORS) * NUM_CLASSES + cls;
    const float4* locb = (const float4*)loc_data + (size_t)b * NUM_PRIORS;
    const float4* pri  = (const float4*)priors;

    // ---- build 64-bit sort keys in registers ---------------------------
    // hi = score bits (positive float -> order-monotonic; 0 if below thresh)
    // lo = ~idx (equal scores sort by ascending original index)
    ull K[SLOTS];
    #pragma unroll
    for (int s = 0; s < SLOTS; s++) {
        int e = s * TPB + t;
        unsigned sb = 0u;
        if (e < NUM_PRIORS) {
            float sc = confb[(size_t)e * NUM_CLASSES];
            if (sc > CONF_THRESH) sb = __float_as_uint(sc);
        }
        K[s] = ((ull)sb << 32) | (unsigned)(~e);
    }

    // ---- bitonic sort (descending), element e = s*TPB + t --------------
    for (unsigned k = 2; k <= SORT_N; k <<= 1) {
        bool descS[SLOTS];
        #pragma unroll
        for (int s = 0; s < SLOTS; s++)
            descS[s] = ((((unsigned)(s * TPB + t)) & k) == 0u);

        // register phases: stride j >= TPB (slot stride inside the thread)
        for (unsigned j = k >> 1; j >= TPB; j >>= 1) {
            unsigned ds = j / TPB;
            #pragma unroll
            for (int s = 0; s < SLOTS; s++) {
                if (!(s & ds)) {
                    int p = s | (int)ds;
                    ull a = K[s], bb = K[p];
                    bool agtb = a > bb;
                    ull mx = agtb ? a : bb;
                    ull mn = agtb ? bb : a;
                    K[s] = descS[s] ? mx : mn;
                    K[p] = descS[s] ? mn : mx;
                }
            }
        }

        // shared phases: 32 <= j <= 256 (cross-warp thread strides)
        if (k > 32u) {
            #pragma unroll
            for (int s = 0; s < SLOTS; s++) keys[s * TPB + t] = K[s];
            __syncthreads();
            unsigned jstart = (k >> 1 < 256u) ? (k >> 1) : 256u;
            for (unsigned j = jstart; j >= 32u; j >>= 1) {
                #pragma unroll
                for (int s = 0; s < SLOTS; s++) {
                    unsigned i = (unsigned)(s * TPB + t);
                    unsigned ixj = i ^ j;
                    if (ixj > i) {
                        ull a = keys[i];
                        ull bb = keys[ixj];
                        bool desc = ((i & k) == 0u);
                        if (desc ? (a < bb) : (a > bb)) {
                            keys[i] = bb;
                            keys[ixj] = a;
                        }
                    }
                }
                __syncthreads();
            }
            #pragma unroll
            for (int s = 0; s < SLOTS; s++) K[s] = keys[s * TPB + t];
        }

        // shfl phases: j <= 16 (lane strides, no smem, no barrier)
        {
            unsigned jtop = (k >> 1 < 16u) ? (k >> 1) : 16u;
            for (unsigned j = jtop; j >= 1u; j >>= 1) {
                bool lower = ((t & (int)j) == 0);
                #pragma unroll
                for (int s = 0; s < SLOTS; s++) {
                    ull mine = K[s];
                    ull oth  = __shfl_xor_sync(FULLM, mine, j);
                    bool keepmax = (lower == descS[s]);
                    bool mgto = mine > oth;
                    K[s] = keepmax ? (mgto ? mine : oth) : (mgto ? oth : mine);
                }
            }
        }
    }
    // dump sorted keys
    #pragma unroll
    for (int s = 0; s < SLOTS; s++) keys[s * TPB + t] = K[s];
    __syncthreads();

    // ---- bulk decode of candidate boxes (ring of DEC_N) ----------------
    // base = 0 now; refilled with upper half if the scan passes DEC_N.
    for (int i = t; i < DEC_N; i += TPB) {
        ull kk = keys[i];
        unsigned sb = (unsigned)(kk >> 32);
        if (sb) {
            int idx = (int)~(unsigned)kk;
            float4 l = locb[idx];
            float4 p = pri[idx];
            float cx = p.x + l.x * 0.1f * p.z;
            float cy = p.y + l.y * 0.1f * p.w;
            float w  = p.z * expf(l.z * 0.2f);
            float h  = p.w * expf(l.w * 0.2f);
            sbox[i] = make_float4(cx - w * 0.5f, cy - h * 0.5f,
                                  cx + w * 0.5f, cy + h * 0.5f);
        }
    }
    __syncthreads();

    // ---- windowed sequential-acceptance scan ---------------------------
    float* orow = out + ((size_t)b * NUM_CLASSES + cls) * TOP_K * 5;
    int nacc = 0, cursor = 0;
    const int lane = t & 31;
    const int g    = t >> 5;     // warp id 0..15

    for (;;) {
        int ci = cursor + lane;                    // this thread's candidate
        ull kk = keys[ci];
        unsigned sb = (unsigned)(kk >> 32);
        bool valid = (sb != 0u);
        float4 cb = sbox[ci & (DEC_N - 1)];
        float  car = (cb.z - cb.x) * (cb.w - cb.y);

        // vs accepted set, strided over the 16 warps
        bool bad = false;
        for (int a = g; a < nacc; a += 16)
            if (overlaps(accb[a], acca[a], cb, car)) { bad = true; break; }
        unsigned badb = __ballot_sync(FULLM, bad && valid);
        if (lane == 0) badp[g] = badb;

        // intra-window transposed overlap rows: this warp owns columns g, g+16
        unsigned valmask = __ballot_sync(FULLM, valid);
        {
            float4 b1 = sbox[(cursor + g) & (DEC_N - 1)];
            float  a1 = (b1.z - b1.x) * (b1.w - b1.y);
            bool o1 = (lane > g) && overlaps(b1, a1, cb, car);
            unsigned ov1 = __ballot_sync(FULLM, o1);
            float4 b2 = sbox[(cursor + g + 16) & (DEC_N - 1)];
            float  a2 = (b2.z - b2.x) * (b2.w - b2.y);
            bool o2 = (lane > g + 16) && overlaps(b2, a2, cb, car);
            unsigned ov2 = __ballot_sync(FULLM, o2);
            if (lane == 0) { ovrT[g] = ov1; ovrT[g + 16] = ov2; }
        }
        __syncthreads();   // B3: ballots staged

        if (t < 32) {
            unsigned myOvrT = ovrT[lane];
            unsigned bm = (lane < 16) ? badp[lane] : 0u;
            unsigned badmask = __reduce_or_sync(FULLM, bm);
            unsigned avail = ~(badmask | ~valmask);
            unsigned m = 0; int cnt = 0; int lim = TOP_K - nacc;
            while (avail && cnt < lim) {
                int i = __ffs(avail) - 1;
                m |= 1u << i; cnt++;
                unsigned ov = __shfl_sync(FULLM, myOvrT, i);
                avail &= ~ov;
                avail &= ~(1u << i);
            }
            // accept-writes straight from registers (candidate == lane)
            if ((m >> lane) & 1u) {
                int slot = nacc + __popc(m & ((1u << lane) - 1u));
                accb[slot] = cb;
                acca[slot] = car;
                float* r = orow + slot * 5;
                r[0] = __uint_as_float(sb);
                r[1] = cb.x; r[2] = cb.y; r[3] = cb.z; r[4] = cb.w;
            }
            if (t == 0) {
                misc[0] = m;
                misc[1] = (valmask != FULLM) ? 1u : 0u;
            }
        }
        __syncthreads();   // B4: accepts + mask visible

        unsigned m = misc[0];
        unsigned dn = misc[1];
        nacc   += __popc(m);
        cursor += 32;
        if (dn || nacc >= TOP_K || cursor >= SORT_N) break;

        // refill the decode ring with the upper half if we cross DEC_N
        if (cursor == DEC_N) {
            for (int i = t; i < DEC_N; i += TPB) {
                ull kk2 = keys[DEC_N + i];
                unsigned sb2 = (unsigned)(kk2 >> 32);
                if (sb2) {
                    int idx = (int)~(unsigned)kk2;
                    float4 l = locb[idx];
                    float4 p = pri[idx];
                    float cx = p.x + l.x * 0.1f * p.z;
                    float cy = p.y + l.y * 0.1f * p.w;
                    float w  = p.z * expf(l.z * 0.2f);
                    float h  = p.w * expf(l.w * 0.2f);
                    sbox[i] = make_float4(cx - w * 0.5f, cy - h * 0.5f,
                                          cx + w * 0.5f, cy + h * 0.5f);
                }
            }
            __syncthreads();
        }
    }
}

extern "C" void kernel_launch(void* const* d_in, const int* in_sizes, int n_in,
                              void* d_out, int out_size)
{
    const float* loc_data  = (const float*)d_in[0];
    const float* conf_data = (const float*)d_in[1];
    const float* priors    = (const float*)d_in[2];
    float* out = (float*)d_out;

    zero_out_kernel<<<1024, 256>>>((float4*)out, out_size / 4);

    cudaFuncSetAttribute((const void*)nms_kernel,
                         cudaFuncAttributeMaxDynamicSharedMemorySize, SMEM_BYTES);
    int nblocks = BATCH * (NUM_CLASSES - 1);   // 5120
    nms_kernel<<<nblocks, TPB, SMEM_BYTES>>>(loc_data, conf_data, priors, out);
}

// round 8
// speedup vs baseline: 6.0625x; 2.4891x over previous
#include <cuda_runtime.h>
#include <math.h>

typedef unsigned long long ull;

#define NUM_PRIORS  3000
#define NUM_CLASSES 21
#define TOP_K       200
#define BATCH       256
#define TPB         512
#define KSLOT       6          // ceil(3000/512)
#define CAP         1024       // fast-path candidate capacity (power of 2)
#define TARGET      896u       // selection target (<= CAP)
#define CONF_THRESH 0.01f
#define NMS_THRESH  0.45f
#define FULLM       0xffffffffu
#define NBC         (BATCH * (NUM_CLASSES - 1))

__device__ unsigned g_flag[NBC];

__global__ void zero_out_kernel(float4* __restrict__ out, int n4)
{
    int i = blockIdx.x * blockDim.x + threadIdx.x;
    int stride = gridDim.x * blockDim.x;
    float4 z = make_float4(0.f, 0.f, 0.f, 0.f);
    for (; i < n4; i += stride) out[i] = z;
}

// identical arithmetic to all previously passing kernels' IoU test
__device__ __forceinline__ bool overlaps(float4 A, float aA, float4 B, float aB)
{
    float ltx = fmaxf(A.x, B.x);
    float lty = fmaxf(A.y, B.y);
    float rbx = fminf(A.z, B.z);
    float rby = fminf(A.w, B.w);
    float iw  = fmaxf(rbx - ltx, 0.f);
    float ih  = fmaxf(rby - lty, 0.f);
    float inter = iw * ih;
    float uni   = aA + aB - inter;
    return inter > NMS_THRESH * uni;
}

// warp-0 helper: over a 256-bin histogram, find the largest bin B such that
// cum(B) = sum_{x>=B} hist[x] >= tgt. Writes misc[0]=B, misc[1]=cum(B+1)
// (count strictly above bin B). Lane 0 writes misc[2] = total (always).
// Caller guarantees a crossing exists whenever misc[0/1] are consumed.
__device__ __forceinline__ void find_bin(const unsigned* hist, unsigned tgt,
                                         unsigned* misc, int lane)
{
    unsigned h[8];
    unsigned s = 0;
    #pragma unroll
    for (int i = 0; i < 8; i++) { h[i] = hist[lane * 8 + i]; s += h[i]; }
    unsigned suf = s;                      // inclusive suffix sum across lanes
    #pragma unroll
    for (int off = 1; off < 32; off <<= 1) {
        unsigned o = __shfl_down_sync(FULLM, suf, off);
        if (lane + off < 32) suf += o;
    }
    unsigned sufnext = __shfl_down_sync(FULLM, suf, 1);
    if (lane == 31) sufnext = 0;
    if (lane == 0) misc[2] = suf;          // total
    if (suf >= tgt && sufnext < tgt) {     // unique crossing lane
        unsigned run = sufnext;
        #pragma unroll
        for (int i = 7; i >= 0; i--) {
            unsigned nr = run + h[i];
            if (nr >= tgt) { misc[0] = (unsigned)(lane * 8 + i); misc[1] = run; break; }
            run = nr;
        }
    }
}

// one bitonic stage (k = KK) over 1024 elements, 2 slots/thread, TPB=512.
// element e = s*512 + t. shfl for j<=16, shared for 32<=j<=256, regs for j=512.
template<unsigned KK>
__device__ __forceinline__ void sort_stage(ull K[2], ull* keys, unsigned t)
{
    bool d0 = ((t & KK) == 0u);
    bool d1 = (((512u + t) & KK) == 0u);
    if constexpr (KK >= 1024u) {           // register phase j = 512
        ull a = K[0], b = K[1];
        bool agtb = a > b;
        ull mx = agtb ? a : b, mn = agtb ? b : a;
        K[0] = d0 ? mx : mn;
        K[1] = d0 ? mn : mx;
    }
    if constexpr (KK >= 64u) {             // shared phases j in [32, min(KK/2,256)]
        keys[t] = K[0]; keys[512u + t] = K[1];
        __syncthreads();
        constexpr unsigned JS = (KK / 2u < 256u) ? KK / 2u : 256u;
        #pragma unroll
        for (unsigned j = JS; j >= 32u; j >>= 1) {
            #pragma unroll
            for (unsigned s = 0; s < 2; s++) {
                unsigned i = s * 512u + t;
                unsigned ixj = i ^ j;
                if (ixj > i) {
                    ull a = keys[i], b = keys[ixj];
                    bool desc = ((i & KK) == 0u);
                    if (desc ? (a < b) : (a > b)) { keys[i] = b; keys[ixj] = a; }
                }
            }
            __syncthreads();
        }
        K[0] = keys[t]; K[1] = keys[512u + t];
    }
    {                                       // shfl phases j <= 16
        constexpr unsigned JT = (KK / 2u < 16u) ? KK / 2u : 16u;
        #pragma unroll
        for (unsigned j = JT; j >= 1u; j >>= 1) {
            bool lower = ((t & j) == 0u);
            {
                ull mine = K[0];
                ull oth  = __shfl_xor_sync(FULLM, mine, j);
                bool keepmax = (lower == d0);
                bool mg = mine > oth;
                K[0] = keepmax ? (mg ? mine : oth) : (mg ? oth : mine);
            }
            {
                ull mine = K[1];
                ull oth  = __shfl_xor_sync(FULLM, mine, j);
                bool keepmax = (lower == d1);
                bool mg = mine > oth;
                K[1] = keepmax ? (mg ? mine : oth) : (mg ? oth : mine);
            }
        }
    }
}

// ---------------------------------------------------------------------------
// Fast path: exact radix-select top-[896,1024] -> sort 1024 -> ordered scan.
// Sets g_flag[bc]=1 iff this CTA's result may be incomplete (handled by the
// slow kernel); 0 otherwise. Every CTA writes its flag exactly once.
// ---------------------------------------------------------------------------
__global__ void __launch_bounds__(TPB, 2)
nms_fast_kernel(const float* __restrict__ loc_data,
                const float* __restrict__ conf_data,
                const float* __restrict__ priors,
                float* __restrict__ out)
{
    __shared__ ull      buf[CAP];        //  8 KB keys
    __shared__ float4   sbox[CAP];       // 16 KB decoded boxes
    __shared__ float4   accb[TOP_K];
    __shared__ float    acca[TOP_K];
    __shared__ unsigned hist[256];
    __shared__ unsigned ovrT[32];
    __shared__ unsigned badp[16];
    __shared__ unsigned misc[4];
    __shared__ int      scnt;

    const int bc   = blockIdx.x;
    const int b    = bc / (NUM_CLASSES - 1);
    const int cls  = bc % (NUM_CLASSES - 1) + 1;
    const unsigned t = threadIdx.x;
    const int lane = t & 31;
    const int g    = t >> 5;

    const float*  confb = conf_data + ((size_t)b * NUM_PRIORS) * NUM_CLASSES + cls;
    const float4* locb  = (const float4*)loc_data + (size_t)b * NUM_PRIORS;
    const float4* pri   = (const float4*)priors;

    // ---- keys + exponent histogram -------------------------------------
    if (t < 256) hist[t] = 0u;
    __syncthreads();

    ull K[KSLOT];
    #pragma unroll
    for (int s = 0; s < KSLOT; s++) {
        int e = s * TPB + (int)t;
        unsigned sb = 0u;
        if (e < NUM_PRIORS) {
            float sc = confb[(size_t)e * NUM_CLASSES];
            if (sc > CONF_THRESH) sb = __float_as_uint(sc);
        }
        K[s] = ((ull)sb << 32) | (unsigned)(~e);
        if (sb) atomicAdd(&hist[sb >> 23], 1u);
    }
    __syncthreads();

    if (t < 32) find_bin(hist, TARGET, misc, lane);
    __syncthreads();

    const unsigned total = misc[2];
    bool overflow = false;
    unsigned T = 0u;

    if (total > CAP) {
        const unsigned E    = misc[0];
        const unsigned cntA = misc[1];
        __syncthreads();                   // find_bin's hist reads done
        if (t < 256) hist[t] = 0u;
        __syncthreads();
        #pragma unroll
        for (int s = 0; s < KSLOT; s++) {
            unsigned sb = (unsigned)(K[s] >> 32);
            if (sb && (sb >> 23) == E) atomicAdd(&hist[(sb >> 15) & 0xFFu], 1u);
        }
        __syncthreads();
        if (t < 32) find_bin(hist, TARGET - cntA, misc, lane);
        __syncthreads();
        const unsigned M = misc[0];
        unsigned sel_est = cntA + misc[1] + hist[M];
        if (sel_est > CAP) overflow = true;
        else T = (E << 23) | (M << 15);
    }

    unsigned needslow = 1u;
    if (!overflow) {
        // ---- compact selected keys -------------------------------------
        if (t == 0) scnt = 0;
        __syncthreads();
        #pragma unroll
        for (int s = 0; s < KSLOT; s++) {
            unsigned sb = (unsigned)(K[s] >> 32);
            if (sb != 0u && sb >= T) {
                int pos = atomicAdd(&scnt, 1);
                if (pos < CAP) buf[pos] = K[s];
            }
        }
        __syncthreads();
        const unsigned selected = (unsigned)scnt;
        for (unsigned i = t; i < CAP; i += TPB)
            if (i >= selected) buf[i] = 0ull;
        __syncthreads();

        // ---- fully-unrolled bitonic sort of 1024 (descending) ----------
        ull S[2];
        S[0] = buf[t]; S[1] = buf[512u + t];
        sort_stage<2u>(S, buf, t);
        sort_stage<4u>(S, buf, t);
        sort_stage<8u>(S, buf, t);
        sort_stage<16u>(S, buf, t);
        sort_stage<32u>(S, buf, t);
        sort_stage<64u>(S, buf, t);
        sort_stage<128u>(S, buf, t);
        sort_stage<256u>(S, buf, t);
        sort_stage<512u>(S, buf, t);
        sort_stage<1024u>(S, buf, t);
        buf[t] = S[0]; buf[512u + t] = S[1];
        __syncthreads();

        // ---- decode selected boxes -------------------------------------
        for (unsigned i = t; i < CAP; i += TPB) {
            ull kk = buf[i];
            unsigned sb = (unsigned)(kk >> 32);
            float4 bb = make_float4(0.f, 0.f, 0.f, 0.f);
            if (sb) {
                int idx = (int)~(unsigned)kk;
                float4 l = locb[idx];
                float4 p = pri[idx];
                float cx = p.x + l.x * 0.1f * p.z;
                float cy = p.y + l.y * 0.1f * p.w;
                float w  = p.z * expf(l.z * 0.2f);
                float h  = p.w * expf(l.w * 0.2f);
                bb = make_float4(cx - w * 0.5f, cy - h * 0.5f,
                                 cx + w * 0.5f, cy + h * 0.5f);
            }
            sbox[i] = bb;
        }
        __syncthreads();

        // ---- windowed sequential-acceptance scan -----------------------
        float* orow = out + ((size_t)b * NUM_CLASSES + cls) * TOP_K * 5;
        int nacc = 0, cursor = 0;
        for (;;) {
            int ci = cursor + lane;
            ull kk = buf[ci];
            unsigned sb = (unsigned)(kk >> 32);
            bool valid = (sb != 0u);
            float4 cb = sbox[ci];
            float  car = (cb.z - cb.x) * (cb.w - cb.y);

            bool bad = false;
            for (int a = g; a < nacc; a += 16)
                if (overlaps(accb[a], acca[a], cb, car)) { bad = true; break; }
            unsigned badb = __ballot_sync(FULLM, bad && valid);
            if (lane == 0) badp[g] = badb;

            unsigned valmask = __ballot_sync(FULLM, valid);
            float4 b1 = sbox[cursor + g];
            float  a1 = (b1.z - b1.x) * (b1.w - b1.y);
            unsigned ov1 = __ballot_sync(FULLM, (lane > g) && overlaps(b1, a1, cb, car));
            float4 b2 = sbox[cursor + g + 16];
            float  a2 = (b2.z - b2.x) * (b2.w - b2.y);
            unsigned ov2 = __ballot_sync(FULLM, (lane > g + 16) && overlaps(b2, a2, cb, car));
            if (lane == 0) { ovrT[g] = ov1; ovrT[g + 16] = ov2; }
            __syncthreads();

            if (t < 32) {
                unsigned myOvrT = ovrT[lane];
                unsigned bm = (lane < 16) ? badp[lane] : 0u;
                unsigned badmask = __reduce_or_sync(FULLM, bm);
                unsigned avail = valmask & ~badmask;
                unsigned m = 0; int cnt = 0; int lim = TOP_K - nacc;
                while (avail && cnt < lim) {
                    int i = __ffs(avail) - 1;
                    m |= 1u << i; cnt++;
                    unsigned ov = __shfl_sync(FULLM, myOvrT, i);
                    avail &= ~ov;
                    avail &= ~(1u << i);
                }
                if ((m >> lane) & 1u) {
                    int slot = nacc + __popc(m & ((1u << lane) - 1u));
                    accb[slot] = cb;
                    acca[slot] = car;
                    float* r = orow + slot * 5;
                    r[0] = __uint_as_float(sb);
                    r[1] = cb.x; r[2] = cb.y; r[3] = cb.z; r[4] = cb.w;
                }
                if (t == 0) {
                    misc[0] = m;
                    misc[1] = (valmask != FULLM) ? 1u : 0u;
                }
            }
            __syncthreads();

            unsigned m = misc[0];
            unsigned dn = misc[1];
            nacc   += __popc(m);
            cursor += 32;
            if (dn || nacc >= TOP_K || cursor >= CAP) break;
        }
        // incomplete only if we ran out of selected candidates while more
        // valid candidates exist below the selection threshold
        needslow = (nacc < TOP_K && total > selected) ? 1u : 0u;
    }
    if (t == 0) g_flag[bc] = needslow;
}

// ---------------------------------------------------------------------------
// Slow path (expected to run ~never): the proven R1 register-argmax NMS,
// gated on g_flag. Rewrites its (b,c) block exactly from scratch.
// ---------------------------------------------------------------------------
#define STPB 256
#define SKPT 12
__global__ void __launch_bounds__(STPB, 2)
nms_slow_kernel(const float* __restrict__ loc_data,
                const float* __restrict__ conf_data,
                const float* __restrict__ priors,
                float* __restrict__ out)
{
    const int bc = blockIdx.x;
    if (g_flag[bc] == 0u) return;

    const int b   = bc / (NUM_CLASSES - 1);
    const int c   = bc % (NUM_CLASSES - 1) + 1;
    const int tid = threadIdx.x;
    const int warp = tid >> 5;
    const int lane = tid & 31;
    const float NEG = -INFINITY;

    float sc[SKPT], bx1[SKPT], by1[SKPT], bx2[SKPT], by2[SKPT], ar[SKPT];
    const float4* locb  = (const float4*)loc_data + (size_t)b * NUM_PRIORS;
    const float4* pri   = (const float4*)priors;
    const float*  confb = conf_data + (size_t)b * NUM_PRIORS * NUM_CLASSES + c;

    #pragma unroll
    for (int k = 0; k < SKPT; k++) {
        int e = k * STPB + tid;
        if (e < NUM_PRIORS) {
            float4 l = locb[e];
            float4 p = pri[e];
            float cx = p.x + l.x * 0.1f * p.z;
            float cy = p.y + l.y * 0.1f * p.w;
            float w  = p.z * expf(l.z * 0.2f);
            float h  = p.w * expf(l.w * 0.2f);
            bx1[k] = cx - w * 0.5f; by1[k] = cy - h * 0.5f;
            bx2[k] = cx + w * 0.5f; by2[k] = cy + h * 0.5f;
            ar[k]  = (bx2[k] - bx1[k]) * (by2[k] - by1[k]);
            float s = confb[(size_t)e * NUM_CLASSES];
            sc[k] = (s > CONF_THRESH) ? s : NEG;
        } else {
            sc[k] = NEG; bx1[k] = by1[k] = bx2[k] = by2[k] = 0.f; ar[k] = 0.f;
        }
    }

    __shared__ float  s_ps[STPB / 32];
    __shared__ int    s_pe[STPB / 32];
    __shared__ float4 s_box;
    float* orow = out + ((size_t)b * NUM_CLASSES + c) * TOP_K * 5;

    for (int it = 0; it < TOP_K; it++) {
        float ls = sc[0]; int lk = 0;
        #pragma unroll
        for (int k = 1; k < SKPT; k++)
            if (sc[k] > ls) { ls = sc[k]; lk = k; }
        int le = lk * STPB + tid;
        #pragma unroll
        for (int off = 16; off; off >>= 1) {
            float os = __shfl_xor_sync(FULLM, ls, off);
            int   oe = __shfl_xor_sync(FULLM, le, off);
            if (os > ls || (os == ls && oe < le)) { ls = os; le = oe; }
        }
        if (lane == 0) { s_ps[warp] = ls; s_pe[warp] = le; }
        __syncthreads();
        float bs = s_ps[0]; int be = s_pe[0];
        #pragma unroll
        for (int w = 1; w < STPB / 32; w++) {
            float os = s_ps[w]; int oe = s_pe[w];
            if (os > bs || (os == bs && oe < be)) { bs = os; be = oe; }
        }
        if (!(bs > CONF_THRESH)) break;
        if (tid == (be & (STPB - 1))) {
            int k = be >> 8;
            s_box = make_float4(bx1[k], by1[k], bx2[k], by2[k]);
            sc[k] = NEG;
            float* r = orow + it * 5;
            r[0] = bs; r[1] = bx1[k]; r[2] = by1[k]; r[3] = bx2[k]; r[4] = by2[k];
        }
        __syncthreads();
        float4 B  = s_box;
        float  A1 = (B.z - B.x) * (B.w - B.y);
        #pragma unroll
        for (int k = 0; k < SKPT; k++) {
            float ltx = fmaxf(B.x, bx1[k]);
            float lty = fmaxf(B.y, by1[k]);
            float rbx = fminf(B.z, bx2[k]);
            float rby = fminf(B.w, by2[k]);
            float iw  = fmaxf(rbx - ltx, 0.f);
            float ih  = fmaxf(rby - lty, 0.f);
            float inter = iw * ih;
            float uni   = A1 + ar[k] - inter;
            if (inter > NMS_THRESH * uni) sc[k] = NEG;
        }
    }
}

extern "C" void kernel_launch(void* const* d_in, const int* in_sizes, int n_in,
                              void* d_out, int out_size)
{
    const float* loc_data  = (const float*)d_in[0];
    const float* conf_data = (const float*)d_in[1];
    const float* priors    = (const float*)d_in[2];
    float* out = (float*)d_out;

    zero_out_kernel<<<1024, 256>>>((float4*)out, out_size / 4);
    nms_fast_kernel<<<NBC, TPB>>>(loc_data, conf_data, priors, out);
    nms_slow_kernel<<<NBC, STPB>>>(loc_data, conf_data, priors, out);
}